// round 1
// baseline (speedup 1.0000x reference)
#include <cuda_runtime.h>
#include <cstdint>
#include <cstddef>

#define BATCH 16
#define CDIM  512
#define EDIM  256
#define NDIM  2048

// ---- scratch (alloc-free rule: __device__ globals) ----
__device__ float g_Aproj[(size_t)BATCH * EDIM * NDIM];
__device__ float g_Bp   [(size_t)BATCH * EDIM * NDIM];
__device__ float g_Bh   [(size_t)BATCH * EDIM * NDIM];
__device__ float g_out1 [(size_t)BATCH * EDIM * NDIM];
__device__ float g_mean [CDIM];
__device__ float g_rstd [CDIM];

// ---- packed f32x2 FMA helpers (FFMA2: PTX-only pattern, 2x fp32 rate) ----
__device__ __forceinline__ unsigned long long dup_f32(float a) {
    unsigned long long r;
    asm("mov.b64 %0, {%1, %1};" : "=l"(r) : "r"(__float_as_uint(a)));
    return r;
}
__device__ __forceinline__ void ffma2(unsigned long long& c,
                                      unsigned long long a,
                                      unsigned long long b) {
    asm("fma.rn.f32x2 %0, %1, %2, %0;" : "+l"(c) : "l"(a), "l"(b));
}

// ============================================================================
// Generic batched 128x128 tile SGEMM, BK=16, 256 threads, 8x8 microtile.
// C[m,n] = alpha * sum_k A(m,k) * B(k,n)
//   A_KMAJ: A addr = m*lda + k   (else: k*lda + m)
//   B_NMAJ: B addr = k*ldb + n   (else: n*ldb + k)
// All dims are multiples of tile sizes for this problem -> no bounds checks.
// ============================================================================
template<bool A_KMAJ, bool B_NMAJ>
__global__ __launch_bounds__(256)
void gemm128x128(const float* __restrict__ Ag, const float* __restrict__ Bg,
                 float* __restrict__ Cg,
                 int K, int lda, int ldb, int ldc,
                 size_t sA, size_t sB, size_t sC, float alpha)
{
    __shared__ __align__(16) float As[16][132];
    __shared__ __align__(16) float Bs[16][132];

    const float* A = Ag + (size_t)blockIdx.z * sA;
    const float* B = Bg + (size_t)blockIdx.z * sB;
    float*       C = Cg + (size_t)blockIdx.z * sC;

    const int m0 = blockIdx.y * 128;
    const int n0 = blockIdx.x * 128;
    const int tid = threadIdx.x;
    const int tx = tid & 15;   // 16 cols of threads -> 8 C-cols each
    const int ty = tid >> 4;   // 16 rows of threads -> 8 C-rows each

    unsigned long long acc[8][4];
    #pragma unroll
    for (int i = 0; i < 8; i++)
        #pragma unroll
        for (int j = 0; j < 4; j++)
            acc[i][j] = 0ull;   // bit pattern of (0.f, 0.f)

    for (int k0 = 0; k0 < K; k0 += 16) {
        // ---- load A tile (128 m x 16 k) into As[k][m] ----
        #pragma unroll
        for (int r = 0; r < 2; r++) {
            int idx = tid + r * 256;
            if (A_KMAJ) {
                int row = idx >> 2;
                int kq  = (idx & 3) << 2;
                float4 v = *(const float4*)(A + (size_t)(m0 + row) * lda + (k0 + kq));
                As[kq + 0][row] = v.x; As[kq + 1][row] = v.y;
                As[kq + 2][row] = v.z; As[kq + 3][row] = v.w;
            } else {
                int kk = idx >> 5;
                int mq = (idx & 31) << 2;
                *(float4*)&As[kk][mq] =
                    *(const float4*)(A + (size_t)(k0 + kk) * lda + (m0 + mq));
            }
        }
        // ---- load B tile (16 k x 128 n) into Bs[k][n] ----
        #pragma unroll
        for (int r = 0; r < 2; r++) {
            int idx = tid + r * 256;
            if (B_NMAJ) {
                int kk = idx >> 5;
                int nq = (idx & 31) << 2;
                *(float4*)&Bs[kk][nq] =
                    *(const float4*)(B + (size_t)(k0 + kk) * ldb + (n0 + nq));
            } else {
                int row = idx >> 2;
                int kq  = (idx & 3) << 2;
                float4 v = *(const float4*)(B + (size_t)(n0 + row) * ldb + (k0 + kq));
                Bs[kq + 0][row] = v.x; Bs[kq + 1][row] = v.y;
                Bs[kq + 2][row] = v.z; Bs[kq + 3][row] = v.w;
            }
        }
        __syncthreads();

        #pragma unroll
        for (int kk = 0; kk < 16; kk++) {
            float a[8];
            *(float4*)&a[0] = *(const float4*)&As[kk][ty * 8];
            *(float4*)&a[4] = *(const float4*)&As[kk][ty * 8 + 4];
            unsigned long long bb[4];
            {
                ulonglong2 t0 = *(const ulonglong2*)&Bs[kk][tx * 8];
                ulonglong2 t1 = *(const ulonglong2*)&Bs[kk][tx * 8 + 4];
                bb[0] = t0.x; bb[1] = t0.y; bb[2] = t1.x; bb[3] = t1.y;
            }
            #pragma unroll
            for (int i = 0; i < 8; i++) {
                unsigned long long aa = dup_f32(a[i]);
                #pragma unroll
                for (int j = 0; j < 4; j++) ffma2(acc[i][j], aa, bb[j]);
            }
        }
        __syncthreads();
    }

    // ---- epilogue ----
    #pragma unroll
    for (int i = 0; i < 8; i++) {
        float o[8];
        #pragma unroll
        for (int j = 0; j < 4; j++) {
            unsigned lo, hi;
            asm("mov.b64 {%0, %1}, %2;" : "=r"(lo), "=r"(hi) : "l"(acc[i][j]));
            o[2 * j]     = __uint_as_float(lo) * alpha;
            o[2 * j + 1] = __uint_as_float(hi) * alpha;
        }
        float* cp = C + (size_t)(m0 + ty * 8 + i) * ldc + (n0 + tx * 8);
        *(float4*)(cp)     = make_float4(o[0], o[1], o[2], o[3]);
        *(float4*)(cp + 4) = make_float4(o[4], o[5], o[6], o[7]);
    }
}

// ============================================================================
// In-place row softmax over rows of length 2048 (one block per row).
// ============================================================================
__global__ __launch_bounds__(256)
void softmax2048(float* __restrict__ att)
{
    float* p = att + (size_t)blockIdx.x * NDIM;
    const int t = threadIdx.x;

    float x[8];
    *(float4*)&x[0] = *(const float4*)(p + t * 4);
    *(float4*)&x[4] = *(const float4*)(p + 1024 + t * 4);

    float mx = x[0];
    #pragma unroll
    for (int i = 1; i < 8; i++) mx = fmaxf(mx, x[i]);
    #pragma unroll
    for (int o = 16; o > 0; o >>= 1) mx = fmaxf(mx, __shfl_xor_sync(0xffffffffu, mx, o));

    __shared__ float rmax[8], rsum[8];
    if ((t & 31) == 0) rmax[t >> 5] = mx;
    __syncthreads();
    mx = rmax[0];
    #pragma unroll
    for (int w = 1; w < 8; w++) mx = fmaxf(mx, rmax[w]);

    float s = 0.f;
    #pragma unroll
    for (int i = 0; i < 8; i++) { x[i] = __expf(x[i] - mx); s += x[i]; }
    #pragma unroll
    for (int o = 16; o > 0; o >>= 1) s += __shfl_xor_sync(0xffffffffu, s, o);
    if ((t & 31) == 0) rsum[t >> 5] = s;
    __syncthreads();
    s = 0.f;
    #pragma unroll
    for (int w = 0; w < 8; w++) s += rsum[w];

    float inv = 1.0f / s;
    #pragma unroll
    for (int i = 0; i < 8; i++) x[i] *= inv;
    *(float4*)(p + t * 4)        = *(float4*)&x[0];
    *(float4*)(p + 1024 + t * 4) = *(float4*)&x[4];
}

// ============================================================================
// BatchNorm: per-channel stats over (batch, positions) = 16*2048 samples.
// ============================================================================
__global__ __launch_bounds__(256)
void bn_stats(const float* __restrict__ outp,
              float* __restrict__ mean, float* __restrict__ rstd)
{
    const int c = blockIdx.x;
    const int t = threadIdx.x;
    float s = 0.f, ss = 0.f;
    for (int b = 0; b < BATCH; b++) {
        const float* p = outp + (size_t)b * CDIM * NDIM + (size_t)c * NDIM;
        for (int a = t; a < NDIM; a += 256) {
            float x = p[a];
            s += x;
            ss = fmaf(x, x, ss);
        }
    }
    #pragma unroll
    for (int o = 16; o > 0; o >>= 1) {
        s  += __shfl_xor_sync(0xffffffffu, s,  o);
        ss += __shfl_xor_sync(0xffffffffu, ss, o);
    }
    __shared__ float rs[8], rss[8];
    if ((t & 31) == 0) { rs[t >> 5] = s; rss[t >> 5] = ss; }
    __syncthreads();
    if (t == 0) {
        float S = 0.f, SS = 0.f;
        #pragma unroll
        for (int w = 0; w < 8; w++) { S += rs[w]; SS += rss[w]; }
        const float invN = 1.0f / (float)(BATCH * NDIM);
        float m = S * invN;
        float var = SS * invN - m * m;
        mean[c] = m;
        rstd[c] = rsqrtf(var + 1e-5f);
    }
}

__global__ __launch_bounds__(256)
void bn_norm(float* __restrict__ outp,
             const float* __restrict__ mean, const float* __restrict__ rstd,
             const float* __restrict__ gamma, const float* __restrict__ beta)
{
    size_t i = ((size_t)blockIdx.x * 256 + threadIdx.x) * 4;
    int c = (int)((i / NDIM) % CDIM);   // NDIM % 4 == 0 -> c constant per float4
    float m = mean[c], r = rstd[c];
    float sc = r * gamma[c];
    float sh = beta[c] - m * sc;
    float4 v = *(float4*)(outp + i);
    v.x = fmaf(v.x, sc, sh);
    v.y = fmaf(v.y, sc, sh);
    v.z = fmaf(v.z, sc, sh);
    v.w = fmaf(v.w, sc, sh);
    *(float4*)(outp + i) = v;
}

// ============================================================================
// launch: out tensor [16,512,2048] first, att [16,2048,2048] second.
// ============================================================================
extern "C" void kernel_launch(void* const* d_in, const int* in_sizes, int n_in,
                              void* d_out, int out_size)
{
    (void)in_sizes; (void)n_in; (void)out_size;
    const float* input_A = (const float*)d_in[0];
    const float* input_B = (const float*)d_in[1];
    const float* W_A     = (const float*)d_in[2];
    const float* W_B     = (const float*)d_in[3];
    const float* W_Bh    = (const float*)d_in[4];
    const float* W_out   = (const float*)d_in[5];
    const float* gamma   = (const float*)d_in[6];
    const float* beta    = (const float*)d_in[7];

    float* out = (float*)d_out;
    float* att = out + (size_t)BATCH * CDIM * NDIM;

    float *aproj, *bp, *bh, *o1, *mean, *rstd;
    cudaGetSymbolAddress((void**)&aproj, g_Aproj);
    cudaGetSymbolAddress((void**)&bp,    g_Bp);
    cudaGetSymbolAddress((void**)&bh,    g_Bh);
    cudaGetSymbolAddress((void**)&o1,    g_out1);
    cudaGetSymbolAddress((void**)&mean,  g_mean);
    cudaGetSymbolAddress((void**)&rstd,  g_rstd);

    const dim3 blk(256);
    const size_t sEN = (size_t)EDIM * NDIM;
    const size_t sCN = (size_t)CDIM * NDIM;
    const size_t sNN = (size_t)NDIM * NDIM;

    // 1) projections: [E,C] x [C,N] per batch (A k-major, B n-major)
    dim3 gp(NDIM / 128, EDIM / 128, BATCH);
    gemm128x128<true, true><<<gp, blk>>>(W_A,  input_A, aproj, CDIM, CDIM, NDIM, NDIM, 0, sCN, sEN, 1.f);
    gemm128x128<true, true><<<gp, blk>>>(W_B,  input_B, bp,    CDIM, CDIM, NDIM, NDIM, 0, sCN, sEN, 1.f);
    gemm128x128<true, true><<<gp, blk>>>(W_Bh, input_B, bh,    CDIM, CDIM, NDIM, NDIM, 0, sCN, sEN, 1.f);

    // 2) h = (Aproj^T · Bp) / 16 -> att logits (A m-major, B n-major), K=E
    dim3 gh(NDIM / 128, NDIM / 128, BATCH);
    gemm128x128<false, true><<<gh, blk>>>(aproj, bp, att, EDIM, NDIM, NDIM, NDIM, sEN, sEN, sNN, 0.0625f);

    // 3) in-place softmax over last dim
    softmax2048<<<BATCH * NDIM, blk>>>(att);

    // 4) out1[e,a] = sum_m Bh[e,m]*att[a,m] (A k-major, B k-major), K=N
    dim3 g3(NDIM / 128, EDIM / 128, BATCH);
    gemm128x128<true, false><<<g3, blk>>>(bh, att, o1, NDIM, NDIM, NDIM, NDIM, sEN, sNN, sEN, 1.f);

    // 5) out_pre = W_out · out1 (A k-major, B n-major), K=E
    dim3 g4(NDIM / 128, CDIM / 128, BATCH);
    gemm128x128<true, true><<<g4, blk>>>(W_out, o1, out, EDIM, EDIM, NDIM, NDIM, 0, sEN, sCN, 1.f);

    // 6) BatchNorm (training-mode stats), in place on out region
    bn_stats<<<CDIM, blk>>>(out, mean, rstd);
    bn_norm<<<(BATCH * CDIM * NDIM) / 1024, blk>>>(out, mean, rstd, gamma, beta);
}

// round 2
// speedup vs baseline: 1.4103x; 1.4103x over previous
#include <cuda_runtime.h>
#include <cstdint>
#include <cstddef>

#define BATCH 16
#define CDIM  512
#define EDIM  256
#define NDIM  2048

// ---- scratch (alloc-free rule: __device__ globals) ----
__device__ float g_Aproj[(size_t)BATCH * EDIM * NDIM];
__device__ float g_Bp   [(size_t)BATCH * EDIM * NDIM];
__device__ float g_Bh   [(size_t)BATCH * EDIM * NDIM];
__device__ float g_out1 [(size_t)BATCH * EDIM * NDIM];
__device__ float g_mean [CDIM];
__device__ float g_rstd [CDIM];

// ---- tf32 helpers ----
__device__ __forceinline__ uint32_t f2tf32(float x) {
    uint32_t r; asm("cvt.rna.tf32.f32 %0, %1;" : "=r"(r) : "f"(x)); return r;
}
__device__ __forceinline__ void mma_tf32(float4& d,
                                         uint32_t a0, uint32_t a1, uint32_t a2, uint32_t a3,
                                         uint32_t b0, uint32_t b1) {
    asm volatile("mma.sync.aligned.m16n8k8.row.col.f32.tf32.tf32.f32 "
                 "{%0,%1,%2,%3}, {%4,%5,%6,%7}, {%8,%9}, {%0,%1,%2,%3};"
                 : "+f"(d.x), "+f"(d.y), "+f"(d.z), "+f"(d.w)
                 : "r"(a0), "r"(a1), "r"(a2), "r"(a3), "r"(b0), "r"(b1));
}

// Fragment-major smem layouts: one conflict-free LDS.128 per operand fragment.
// A tile 128(m) x 32(k): slab = (ks 0..3, ms 0..7) of 16m x 8k.
//   mma A-frag lane = (m%8)*4 + (k%4);  reg = (m/8)%2 + 2*((k/8?:)(k%8)/4)
__device__ __forceinline__ int a_idx(int m, int k) {
    int ms = m >> 4, mi = m & 15, ks = k >> 3, ki = k & 7;
    int lane = ((mi & 7) << 2) | (ki & 3);
    int reg  = (mi >> 3) | ((ki >> 2) << 1);
    return (((ks << 3) | ms) << 7) | (lane << 2) | reg;
}
// B tile 32(k) x 128(n): slab = 8k x 8n; pairs of n-slabs packed for LDS.128.
//   mma B-frag lane = n*4 + (k%4); reg = (k%8)/4, pair-select in bit1.
__device__ __forceinline__ int b_idx(int k, int n) {
    int ks = k >> 3, ki = k & 7, ns = n >> 3, ni = n & 7;
    int jp = ns >> 1, p = ns & 1;
    int lane = (ni << 2) | (ki & 3);
    int reg  = (ki >> 2) | (p << 1);
    return (((ks << 3) | jp) << 7) | (lane << 2) | reg;
}

// ============================================================================
// Batched TF32 tensor-core GEMM: 128x128 block tile, BK=32, 256 threads,
// 8 warps in 2x4, warp tile 64x32, m16n8k8 fragments.
// C[m,n] = alpha * sum_k A(m,k)*B(k,n)
//   A_KMAJ: A addr = m*lda + k (else k*lda + m)
//   B_NMAJ: B addr = k*ldb + n (else n*ldb + k)
// ============================================================================
template<bool A_KMAJ, bool B_NMAJ>
__global__ __launch_bounds__(256, 2)
void gemm_tf32(const float* __restrict__ Ag, const float* __restrict__ Bg,
               float* __restrict__ Cg, int K, int lda, int ldb, int ldc,
               size_t sA, size_t sB, size_t sC, float alpha)
{
    __shared__ __align__(16) uint32_t As[4096];
    __shared__ __align__(16) uint32_t Bs[4096];

    const float* A = Ag + (size_t)blockIdx.z * sA;
    const float* B = Bg + (size_t)blockIdx.z * sB;
    float*       C = Cg + (size_t)blockIdx.z * sC;

    const int m0 = blockIdx.y * 128;
    const int n0 = blockIdx.x * 128;
    const int tid = threadIdx.x;
    const int lane = tid & 31;
    const int wid = tid >> 5;
    const int warp_m = wid >> 2;   // 0..1 -> 64 rows
    const int warp_n = wid & 3;    // 0..3 -> 32 cols

    float4 acc[4][4];
    #pragma unroll
    for (int i = 0; i < 4; i++)
        #pragma unroll
        for (int j = 0; j < 4; j++)
            acc[i][j] = make_float4(0.f, 0.f, 0.f, 0.f);

    for (int k0 = 0; k0 < K; k0 += 32) {
        // ---- stage A tile into fragment order ----
        if (A_KMAJ) {
            #pragma unroll
            for (int r = 0; r < 4; r++) {
                int idx = tid + (r << 8);          // 0..1023
                int m = idx >> 3, kq = (idx & 7) << 2;
                float4 v = *(const float4*)(A + (size_t)(m0 + m) * lda + (k0 + kq));
                As[a_idx(m, kq + 0)] = f2tf32(v.x);
                As[a_idx(m, kq + 1)] = f2tf32(v.y);
                As[a_idx(m, kq + 2)] = f2tf32(v.z);
                As[a_idx(m, kq + 3)] = f2tf32(v.w);
            }
        } else {
            #pragma unroll
            for (int r = 0; r < 4; r++) {
                int idx = tid + (r << 8);
                int k = idx >> 5, mq = (idx & 31) << 2;
                float4 v = *(const float4*)(A + (size_t)(k0 + k) * lda + (m0 + mq));
                As[a_idx(mq + 0, k)] = f2tf32(v.x);
                As[a_idx(mq + 1, k)] = f2tf32(v.y);
                As[a_idx(mq + 2, k)] = f2tf32(v.z);
                As[a_idx(mq + 3, k)] = f2tf32(v.w);
            }
        }
        // ---- stage B tile into fragment order ----
        if (B_NMAJ) {
            #pragma unroll
            for (int r = 0; r < 4; r++) {
                int idx = tid + (r << 8);
                int k = idx >> 5, nq = (idx & 31) << 2;
                float4 v = *(const float4*)(B + (size_t)(k0 + k) * ldb + (n0 + nq));
                Bs[b_idx(k, nq + 0)] = f2tf32(v.x);
                Bs[b_idx(k, nq + 1)] = f2tf32(v.y);
                Bs[b_idx(k, nq + 2)] = f2tf32(v.z);
                Bs[b_idx(k, nq + 3)] = f2tf32(v.w);
            }
        } else {
            #pragma unroll
            for (int r = 0; r < 4; r++) {
                int idx = tid + (r << 8);
                int n = idx >> 3, kq = (idx & 7) << 2;
                float4 v = *(const float4*)(B + (size_t)(n0 + n) * ldb + (k0 + kq));
                Bs[b_idx(kq + 0, n)] = f2tf32(v.x);
                Bs[b_idx(kq + 1, n)] = f2tf32(v.y);
                Bs[b_idx(kq + 2, n)] = f2tf32(v.z);
                Bs[b_idx(kq + 3, n)] = f2tf32(v.w);
            }
        }
        __syncthreads();

        #pragma unroll
        for (int ks = 0; ks < 4; ks++) {
            uint4 af[4];
            uint4 bf[2];
            #pragma unroll
            for (int i = 0; i < 4; i++)
                af[i] = *(const uint4*)&As[(((ks << 3) | (warp_m * 4 + i)) << 7) | (lane << 2)];
            #pragma unroll
            for (int j = 0; j < 2; j++)
                bf[j] = *(const uint4*)&Bs[(((ks << 3) | (warp_n * 2 + j)) << 7) | (lane << 2)];
            #pragma unroll
            for (int i = 0; i < 4; i++) {
                #pragma unroll
                for (int jn = 0; jn < 4; jn++) {
                    uint32_t b0 = (jn & 1) ? bf[jn >> 1].z : bf[jn >> 1].x;
                    uint32_t b1 = (jn & 1) ? bf[jn >> 1].w : bf[jn >> 1].y;
                    mma_tf32(acc[i][jn], af[i].x, af[i].y, af[i].z, af[i].w, b0, b1);
                }
            }
        }
        __syncthreads();
    }

    // ---- epilogue ----
    const int g = lane >> 2, t = lane & 3;
    const int mw = m0 + warp_m * 64;
    const int nw = n0 + warp_n * 32;
    #pragma unroll
    for (int i = 0; i < 4; i++) {
        #pragma unroll
        for (int jn = 0; jn < 4; jn++) {
            int row = mw + i * 16 + g;
            int col = nw + jn * 8 + 2 * t;
            *(float2*)(C + (size_t)row * ldc + col) =
                make_float2(acc[i][jn].x * alpha, acc[i][jn].y * alpha);
            *(float2*)(C + (size_t)(row + 8) * ldc + col) =
                make_float2(acc[i][jn].z * alpha, acc[i][jn].w * alpha);
        }
    }
}

// ============================================================================
// In-place row softmax over rows of length 2048 (one block per row).
// ============================================================================
__global__ __launch_bounds__(256)
void softmax2048(float* __restrict__ att)
{
    float* p = att + (size_t)blockIdx.x * NDIM;
    const int t = threadIdx.x;

    float x[8];
    *(float4*)&x[0] = *(const float4*)(p + t * 4);
    *(float4*)&x[4] = *(const float4*)(p + 1024 + t * 4);

    float mx = x[0];
    #pragma unroll
    for (int i = 1; i < 8; i++) mx = fmaxf(mx, x[i]);
    #pragma unroll
    for (int o = 16; o > 0; o >>= 1) mx = fmaxf(mx, __shfl_xor_sync(0xffffffffu, mx, o));

    __shared__ float rmax[8], rsum[8];
    if ((t & 31) == 0) rmax[t >> 5] = mx;
    __syncthreads();
    mx = rmax[0];
    #pragma unroll
    for (int w = 1; w < 8; w++) mx = fmaxf(mx, rmax[w]);

    float s = 0.f;
    #pragma unroll
    for (int i = 0; i < 8; i++) { x[i] = __expf(x[i] - mx); s += x[i]; }
    #pragma unroll
    for (int o = 16; o > 0; o >>= 1) s += __shfl_xor_sync(0xffffffffu, s, o);
    if ((t & 31) == 0) rsum[t >> 5] = s;
    __syncthreads();
    s = 0.f;
    #pragma unroll
    for (int w = 0; w < 8; w++) s += rsum[w];

    float inv = 1.0f / s;
    #pragma unroll
    for (int i = 0; i < 8; i++) x[i] *= inv;
    *(float4*)(p + t * 4)        = *(float4*)&x[0];
    *(float4*)(p + 1024 + t * 4) = *(float4*)&x[4];
}

// ============================================================================
// BatchNorm: per-channel stats over (batch, positions) = 16*2048 samples.
// ============================================================================
__global__ __launch_bounds__(256)
void bn_stats(const float* __restrict__ outp,
              float* __restrict__ mean, float* __restrict__ rstd)
{
    const int c = blockIdx.x;
    const int t = threadIdx.x;
    float s = 0.f, ss = 0.f;
    for (int b = 0; b < BATCH; b++) {
        const float* p = outp + (size_t)b * CDIM * NDIM + (size_t)c * NDIM;
        for (int a = t; a < NDIM; a += 256) {
            float x = p[a];
            s += x;
            ss = fmaf(x, x, ss);
        }
    }
    #pragma unroll
    for (int o = 16; o > 0; o >>= 1) {
        s  += __shfl_xor_sync(0xffffffffu, s,  o);
        ss += __shfl_xor_sync(0xffffffffu, ss, o);
    }
    __shared__ float rs[8], rss[8];
    if ((t & 31) == 0) { rs[t >> 5] = s; rss[t >> 5] = ss; }
    __syncthreads();
    if (t == 0) {
        float S = 0.f, SS = 0.f;
        #pragma unroll
        for (int w = 0; w < 8; w++) { S += rs[w]; SS += rss[w]; }
        const float invN = 1.0f / (float)(BATCH * NDIM);
        float m = S * invN;
        float var = SS * invN - m * m;
        mean[c] = m;
        rstd[c] = rsqrtf(var + 1e-5f);
    }
}

__global__ __launch_bounds__(256)
void bn_norm(float* __restrict__ outp,
             const float* __restrict__ mean, const float* __restrict__ rstd,
             const float* __restrict__ gamma, const float* __restrict__ beta)
{
    size_t i = ((size_t)blockIdx.x * 256 + threadIdx.x) * 4;
    int c = (int)((i / NDIM) % CDIM);
    float m = mean[c], r = rstd[c];
    float sc = r * gamma[c];
    float sh = beta[c] - m * sc;
    float4 v = *(float4*)(outp + i);
    v.x = fmaf(v.x, sc, sh);
    v.y = fmaf(v.y, sc, sh);
    v.z = fmaf(v.z, sc, sh);
    v.w = fmaf(v.w, sc, sh);
    *(float4*)(outp + i) = v;
}

// ============================================================================
// launch: out tensor [16,512,2048] first, att [16,2048,2048] second.
// ============================================================================
extern "C" void kernel_launch(void* const* d_in, const int* in_sizes, int n_in,
                              void* d_out, int out_size)
{
    (void)in_sizes; (void)n_in; (void)out_size;
    const float* input_A = (const float*)d_in[0];
    const float* input_B = (const float*)d_in[1];
    const float* W_A     = (const float*)d_in[2];
    const float* W_B     = (const float*)d_in[3];
    const float* W_Bh    = (const float*)d_in[4];
    const float* W_out   = (const float*)d_in[5];
    const float* gamma   = (const float*)d_in[6];
    const float* beta    = (const float*)d_in[7];

    float* out = (float*)d_out;
    float* att = out + (size_t)BATCH * CDIM * NDIM;

    float *aproj, *bp, *bh, *o1, *mean, *rstd;
    cudaGetSymbolAddress((void**)&aproj, g_Aproj);
    cudaGetSymbolAddress((void**)&bp,    g_Bp);
    cudaGetSymbolAddress((void**)&bh,    g_Bh);
    cudaGetSymbolAddress((void**)&o1,    g_out1);
    cudaGetSymbolAddress((void**)&mean,  g_mean);
    cudaGetSymbolAddress((void**)&rstd,  g_rstd);

    const dim3 blk(256);
    const size_t sEN = (size_t)EDIM * NDIM;
    const size_t sCN = (size_t)CDIM * NDIM;
    const size_t sNN = (size_t)NDIM * NDIM;

    // 1) projections: [E,C] x [C,N] per batch (A k-major, B n-major)
    dim3 gp(NDIM / 128, EDIM / 128, BATCH);
    gemm_tf32<true, true><<<gp, blk>>>(W_A,  input_A, aproj, CDIM, CDIM, NDIM, NDIM, 0, sCN, sEN, 1.f);
    gemm_tf32<true, true><<<gp, blk>>>(W_B,  input_B, bp,    CDIM, CDIM, NDIM, NDIM, 0, sCN, sEN, 1.f);
    gemm_tf32<true, true><<<gp, blk>>>(W_Bh, input_B, bh,    CDIM, CDIM, NDIM, NDIM, 0, sCN, sEN, 1.f);

    // 2) h = (Aproj^T · Bp) / 16 -> att logits (A m-major, B n-major), K=E
    dim3 gh(NDIM / 128, NDIM / 128, BATCH);
    gemm_tf32<false, true><<<gh, blk>>>(aproj, bp, att, EDIM, NDIM, NDIM, NDIM, sEN, sEN, sNN, 0.0625f);

    // 3) in-place softmax over last dim
    softmax2048<<<BATCH * NDIM, blk>>>(att);

    // 4) out1[e,a] = sum_m Bh[e,m]*att[a,m] (A k-major, B k-major/transposed), K=N
    dim3 g3(NDIM / 128, EDIM / 128, BATCH);
    gemm_tf32<true, false><<<g3, blk>>>(bh, att, o1, NDIM, NDIM, NDIM, NDIM, sEN, sNN, sEN, 1.f);

    // 5) out_pre = W_out · out1 (A k-major, B n-major), K=E
    dim3 g4(NDIM / 128, CDIM / 128, BATCH);
    gemm_tf32<true, true><<<g4, blk>>>(W_out, o1, out, EDIM, EDIM, NDIM, NDIM, 0, sEN, sCN, 1.f);

    // 6) BatchNorm (training-mode stats), in place on out region
    bn_stats<<<CDIM, blk>>>(out, mean, rstd);
    bn_norm<<<(BATCH * CDIM * NDIM) / 1024, blk>>>(out, mean, rstd, gamma, beta);
}

// round 3
// speedup vs baseline: 2.4336x; 1.7255x over previous
#include <cuda_runtime.h>
#include <cstdint>
#include <cstddef>

#define BATCH 16
#define CDIM  512
#define EDIM  256
#define NDIM  2048

// ---- scratch (alloc-free rule: __device__ globals) ----
__device__ float g_Aproj[(size_t)BATCH * EDIM * NDIM];
__device__ float g_Bp   [(size_t)BATCH * EDIM * NDIM];
__device__ float g_Bh   [(size_t)BATCH * EDIM * NDIM];
__device__ float g_out1 [(size_t)BATCH * EDIM * NDIM];
__device__ float g_mean [CDIM];
__device__ float g_rstd [CDIM];

// ---- tf32 / mma helpers ----
__device__ __forceinline__ uint32_t f2tf32(float x) {
    uint32_t r; asm("cvt.rna.tf32.f32 %0, %1;" : "=r"(r) : "f"(x)); return r;
}
__device__ __forceinline__ void mma_tf32(float4& d,
                                         uint32_t a0, uint32_t a1, uint32_t a2, uint32_t a3,
                                         uint32_t b0, uint32_t b1) {
    asm volatile("mma.sync.aligned.m16n8k8.row.col.f32.tf32.tf32.f32 "
                 "{%0,%1,%2,%3}, {%4,%5,%6,%7}, {%8,%9}, {%0,%1,%2,%3};"
                 : "+f"(d.x), "+f"(d.y), "+f"(d.z), "+f"(d.w)
                 : "r"(a0), "r"(a1), "r"(a2), "r"(a3), "r"(b0), "r"(b1));
}
__device__ __forceinline__ void ldsm_x4(uint32_t& r0, uint32_t& r1,
                                        uint32_t& r2, uint32_t& r3, uint32_t addr) {
    asm volatile("ldmatrix.sync.aligned.m8n8.x4.shared.b16 {%0,%1,%2,%3}, [%4];"
                 : "=r"(r0), "=r"(r1), "=r"(r2), "=r"(r3) : "r"(addr));
}

// swizzle for 128B rows: XOR byte-col bits[4:6] with row bits[0:2]
__device__ __forceinline__ uint32_t swz(uint32_t row, uint32_t colbyte) {
    return (row << 7) | (colbyte ^ ((row & 7) << 4));
}

// ============================================================================
// Batched TF32 tensor-core GEMM: 128x128 block tile, BK=32, 256 threads,
// 8 warps (2x4), warp tile 64x32, m16n8k8, ldmatrix-fed fragments.
// C[m,n] = alpha * sum_k A(m,k)*B(k,n)
//   A_KMAJ: A addr = m*lda + k (else k*lda + m)
//   B_NMAJ: B addr = k*ldb + n (else n*ldb + k)
// Smem: As = 128 m-rows x 32 k (128B rows, swizzled); Bs = 128 n-rows x 32 k.
// ============================================================================
template<bool A_KMAJ, bool B_NMAJ>
__global__ __launch_bounds__(256, 2)
void gemm_tf32(const float* __restrict__ Ag, const float* __restrict__ Bg,
               float* __restrict__ Cg, int K, int lda, int ldb, int ldc,
               size_t sA, size_t sB, size_t sC, float alpha)
{
    __shared__ __align__(16) uint32_t As[128 * 32];
    __shared__ __align__(16) uint32_t Bs[128 * 32];

    const float* A = Ag + (size_t)blockIdx.z * sA;
    const float* B = Bg + (size_t)blockIdx.z * sB;
    float*       C = Cg + (size_t)blockIdx.z * sC;

    const int m0 = blockIdx.y * 128;
    const int n0 = blockIdx.x * 128;
    const int tid  = threadIdx.x;
    const int lane = tid & 31;
    const int wid  = tid >> 5;
    const int warp_m = wid >> 2;   // 0..1  -> 64 m-rows
    const int warp_n = wid & 3;    // 0..3  -> 32 n-cols

    const uint32_t smA = (uint32_t)__cvta_generic_to_shared(As);
    const uint32_t smB = (uint32_t)__cvta_generic_to_shared(Bs);

    // per-lane ldmatrix row/half selectors
    const int a_row = (lane & 7) + ((lane >> 3) & 1) * 8;  // T0/T2 rows 0-7, T1/T3 rows 8-15
    const int a_ts  = ((lane >> 4) & 1) << 4;              // byte half within 8k (0/16)
    const int b_row = (lane & 7) + ((lane >> 4) & 1) * 8;
    const int b_ts  = ((lane >> 3) & 1) << 4;

    // per-lane row-base addresses (col part added per ks)
    uint32_t aAddr[4], bAddr[2];
    #pragma unroll
    for (int i = 0; i < 4; i++) {
        int row = warp_m * 64 + i * 16 + a_row;
        aAddr[i] = smA + (row << 7);
    }
    #pragma unroll
    for (int j = 0; j < 2; j++) {
        int row = warp_n * 32 + j * 16 + b_row;
        bAddr[j] = smB + (row << 7);
    }
    const uint32_t aSwz = (uint32_t)((a_row & 7) << 4);
    const uint32_t bSwz = (uint32_t)((b_row & 7) << 4);

    float4 acc[4][4];
    #pragma unroll
    for (int i = 0; i < 4; i++)
        #pragma unroll
        for (int j = 0; j < 4; j++)
            acc[i][j] = make_float4(0.f, 0.f, 0.f, 0.f);

    for (int k0 = 0; k0 < K; k0 += 32) {
        // ---- stage A tile: As[m][k], one STS.128 per 4 elems ----
        if (A_KMAJ) {
            #pragma unroll
            for (int r = 0; r < 4; r++) {
                int idx = tid + (r << 8);
                int row = idx >> 3;            // m 0..127
                int kq  = (idx & 7) << 2;      // k 0,4,..,28
                float4 v = *(const float4*)(A + (size_t)(m0 + row) * lda + (k0 + kq));
                uint4 w = make_uint4(f2tf32(v.x), f2tf32(v.y), f2tf32(v.z), f2tf32(v.w));
                *(uint4*)((char*)As + swz(row, kq << 2)) = w;
            }
        } else {
            #pragma unroll
            for (int r = 0; r < 4; r++) {
                int idx = tid + (r << 8);
                int m  = idx & 127;
                int kq = (idx >> 7) << 2;
                const float* p = A + (size_t)(k0 + kq) * lda + (m0 + m);
                uint4 w = make_uint4(f2tf32(p[0]), f2tf32(p[lda]),
                                     f2tf32(p[2 * (size_t)lda]), f2tf32(p[3 * (size_t)lda]));
                *(uint4*)((char*)As + swz(m, kq << 2)) = w;
            }
        }
        // ---- stage B tile: Bs[n][k] ----
        if (B_NMAJ) {
            #pragma unroll
            for (int r = 0; r < 4; r++) {
                int idx = tid + (r << 8);
                int n  = idx & 127;
                int kq = (idx >> 7) << 2;
                const float* p = B + (size_t)(k0 + kq) * ldb + (n0 + n);
                uint4 w = make_uint4(f2tf32(p[0]), f2tf32(p[ldb]),
                                     f2tf32(p[2 * (size_t)ldb]), f2tf32(p[3 * (size_t)ldb]));
                *(uint4*)((char*)Bs + swz(n, kq << 2)) = w;
            }
        } else {
            #pragma unroll
            for (int r = 0; r < 4; r++) {
                int idx = tid + (r << 8);
                int row = idx >> 3;            // n 0..127
                int kq  = (idx & 7) << 2;
                float4 v = *(const float4*)(B + (size_t)(n0 + row) * ldb + (k0 + kq));
                uint4 w = make_uint4(f2tf32(v.x), f2tf32(v.y), f2tf32(v.z), f2tf32(v.w));
                *(uint4*)((char*)Bs + swz(row, kq << 2)) = w;
            }
        }
        __syncthreads();

        // ---- compute: 4 k-slices of 8 ----
        #pragma unroll
        for (int ks = 0; ks < 4; ks++) {
            const uint32_t aCol = ((uint32_t)(ks * 32) + a_ts) ^ aSwz;
            const uint32_t bCol = ((uint32_t)(ks * 32) + b_ts) ^ bSwz;
            uint32_t af[4][4];
            #pragma unroll
            for (int i = 0; i < 4; i++)
                ldsm_x4(af[i][0], af[i][1], af[i][2], af[i][3], aAddr[i] + aCol);
            uint32_t bf[2][4];
            #pragma unroll
            for (int j = 0; j < 2; j++)
                ldsm_x4(bf[j][0], bf[j][1], bf[j][2], bf[j][3], bAddr[j] + bCol);
            #pragma unroll
            for (int i = 0; i < 4; i++) {
                #pragma unroll
                for (int jn = 0; jn < 4; jn++) {
                    int jx = jn >> 1, h = (jn & 1) << 1;   // bf[jx][h]=b0, bf[jx][h+1]=b1
                    mma_tf32(acc[i][jn], af[i][0], af[i][1], af[i][2], af[i][3],
                             bf[jx][h], bf[jx][h + 1]);
                }
            }
        }
        __syncthreads();
    }

    // ---- epilogue ----
    const int g = lane >> 2, t = lane & 3;
    const int mw = m0 + warp_m * 64;
    const int nw = n0 + warp_n * 32;
    #pragma unroll
    for (int i = 0; i < 4; i++) {
        #pragma unroll
        for (int jn = 0; jn < 4; jn++) {
            int row = mw + i * 16 + g;
            int col = nw + jn * 8 + 2 * t;
            *(float2*)(C + (size_t)row * ldc + col) =
                make_float2(acc[i][jn].x * alpha, acc[i][jn].y * alpha);
            *(float2*)(C + (size_t)(row + 8) * ldc + col) =
                make_float2(acc[i][jn].z * alpha, acc[i][jn].w * alpha);
        }
    }
}

// ============================================================================
// In-place row softmax over rows of length 2048 (one block per row).
// ============================================================================
__global__ __launch_bounds__(256)
void softmax2048(float* __restrict__ att)
{
    float* p = att + (size_t)blockIdx.x * NDIM;
    const int t = threadIdx.x;

    float x[8];
    *(float4*)&x[0] = *(const float4*)(p + t * 4);
    *(float4*)&x[4] = *(const float4*)(p + 1024 + t * 4);

    float mx = x[0];
    #pragma unroll
    for (int i = 1; i < 8; i++) mx = fmaxf(mx, x[i]);
    #pragma unroll
    for (int o = 16; o > 0; o >>= 1) mx = fmaxf(mx, __shfl_xor_sync(0xffffffffu, mx, o));

    __shared__ float rmax[8], rsum[8];
    if ((t & 31) == 0) rmax[t >> 5] = mx;
    __syncthreads();
    mx = rmax[0];
    #pragma unroll
    for (int w = 1; w < 8; w++) mx = fmaxf(mx, rmax[w]);

    float s = 0.f;
    #pragma unroll
    for (int i = 0; i < 8; i++) { x[i] = __expf(x[i] - mx); s += x[i]; }
    #pragma unroll
    for (int o = 16; o > 0; o >>= 1) s += __shfl_xor_sync(0xffffffffu, s, o);
    if ((t & 31) == 0) rsum[t >> 5] = s;
    __syncthreads();
    s = 0.f;
    #pragma unroll
    for (int w = 0; w < 8; w++) s += rsum[w];

    float inv = 1.0f / s;
    #pragma unroll
    for (int i = 0; i < 8; i++) x[i] *= inv;
    *(float4*)(p + t * 4)        = *(float4*)&x[0];
    *(float4*)(p + 1024 + t * 4) = *(float4*)&x[4];
}

// ============================================================================
// BatchNorm: per-channel stats over (batch, positions) = 16*2048 samples.
// ============================================================================
__global__ __launch_bounds__(256)
void bn_stats(const float* __restrict__ outp,
              float* __restrict__ mean, float* __restrict__ rstd)
{
    const int c = blockIdx.x;
    const int t = threadIdx.x;
    float s = 0.f, ss = 0.f;
    for (int b = 0; b < BATCH; b++) {
        const float* p = outp + (size_t)b * CDIM * NDIM + (size_t)c * NDIM;
        for (int a = t; a < NDIM; a += 256) {
            float x = p[a];
            s += x;
            ss = fmaf(x, x, ss);
        }
    }
    #pragma unroll
    for (int o = 16; o > 0; o >>= 1) {
        s  += __shfl_xor_sync(0xffffffffu, s,  o);
        ss += __shfl_xor_sync(0xffffffffu, ss, o);
    }
    __shared__ float rs[8], rss[8];
    if ((t & 31) == 0) { rs[t >> 5] = s; rss[t >> 5] = ss; }
    __syncthreads();
    if (t == 0) {
        float S = 0.f, SS = 0.f;
        #pragma unroll
        for (int w = 0; w < 8; w++) { S += rs[w]; SS += rss[w]; }
        const float invN = 1.0f / (float)(BATCH * NDIM);
        float m = S * invN;
        float var = SS * invN - m * m;
        mean[c] = m;
        rstd[c] = rsqrtf(var + 1e-5f);
    }
}

__global__ __launch_bounds__(256)
void bn_norm(float* __restrict__ outp,
             const float* __restrict__ mean, const float* __restrict__ rstd,
             const float* __restrict__ gamma, const float* __restrict__ beta)
{
    size_t i = ((size_t)blockIdx.x * 256 + threadIdx.x) * 4;
    int c = (int)((i / NDIM) % CDIM);
    float m = mean[c], r = rstd[c];
    float sc = r * gamma[c];
    float sh = beta[c] - m * sc;
    float4 v = *(float4*)(outp + i);
    v.x = fmaf(v.x, sc, sh);
    v.y = fmaf(v.y, sc, sh);
    v.z = fmaf(v.z, sc, sh);
    v.w = fmaf(v.w, sc, sh);
    *(float4*)(outp + i) = v;
}

// ============================================================================
// launch: out tensor [16,512,2048] first, att [16,2048,2048] second.
// ============================================================================
extern "C" void kernel_launch(void* const* d_in, const int* in_sizes, int n_in,
                              void* d_out, int out_size)
{
    (void)in_sizes; (void)n_in; (void)out_size;
    const float* input_A = (const float*)d_in[0];
    const float* input_B = (const float*)d_in[1];
    const float* W_A     = (const float*)d_in[2];
    const float* W_B     = (const float*)d_in[3];
    const float* W_Bh    = (const float*)d_in[4];
    const float* W_out   = (const float*)d_in[5];
    const float* gamma   = (const float*)d_in[6];
    const float* beta    = (const float*)d_in[7];

    float* out = (float*)d_out;
    float* att = out + (size_t)BATCH * CDIM * NDIM;

    float *aproj, *bp, *bh, *o1, *mean, *rstd;
    cudaGetSymbolAddress((void**)&aproj, g_Aproj);
    cudaGetSymbolAddress((void**)&bp,    g_Bp);
    cudaGetSymbolAddress((void**)&bh,    g_Bh);
    cudaGetSymbolAddress((void**)&o1,    g_out1);
    cudaGetSymbolAddress((void**)&mean,  g_mean);
    cudaGetSymbolAddress((void**)&rstd,  g_rstd);

    const dim3 blk(256);
    const size_t sEN = (size_t)EDIM * NDIM;
    const size_t sCN = (size_t)CDIM * NDIM;
    const size_t sNN = (size_t)NDIM * NDIM;

    // 1) projections: [E,C] x [C,N] per batch (A k-major, B n-major)
    dim3 gp(NDIM / 128, EDIM / 128, BATCH);
    gemm_tf32<true, true><<<gp, blk>>>(W_A,  input_A, aproj, CDIM, CDIM, NDIM, NDIM, 0, sCN, sEN, 1.f);
    gemm_tf32<true, true><<<gp, blk>>>(W_B,  input_B, bp,    CDIM, CDIM, NDIM, NDIM, 0, sCN, sEN, 1.f);
    gemm_tf32<true, true><<<gp, blk>>>(W_Bh, input_B, bh,    CDIM, CDIM, NDIM, NDIM, 0, sCN, sEN, 1.f);

    // 2) h = (Aproj^T · Bp) / 16 -> att logits (A m-major, B n-major), K=E
    dim3 gh(NDIM / 128, NDIM / 128, BATCH);
    gemm_tf32<false, true><<<gh, blk>>>(aproj, bp, att, EDIM, NDIM, NDIM, NDIM, sEN, sEN, sNN, 0.0625f);

    // 3) in-place softmax over last dim
    softmax2048<<<BATCH * NDIM, blk>>>(att);

    // 4) out1[e,a] = sum_m Bh[e,m]*att[a,m] (A k-major, B k-major), K=N
    dim3 g3(NDIM / 128, EDIM / 128, BATCH);
    gemm_tf32<true, false><<<g3, blk>>>(bh, att, o1, NDIM, NDIM, NDIM, NDIM, sEN, sNN, sEN, 1.f);

    // 5) out_pre = W_out · out1 (A k-major, B n-major), K=E
    dim3 g4(NDIM / 128, CDIM / 128, BATCH);
    gemm_tf32<true, true><<<g4, blk>>>(W_out, o1, out, EDIM, EDIM, NDIM, NDIM, 0, sEN, sCN, 1.f);

    // 6) BatchNorm (training-mode stats), in place on out region
    bn_stats<<<CDIM, blk>>>(out, mean, rstd);
    bn_norm<<<(BATCH * CDIM * NDIM) / 1024, blk>>>(out, mean, rstd, gamma, beta);
}

// round 4
// speedup vs baseline: 3.3623x; 1.3816x over previous
#include <cuda_runtime.h>
#include <cstdint>
#include <cstddef>

#define BATCH 16
#define CDIM  512
#define EDIM  256
#define NDIM  2048
#define STAGES 3
#define STAGE_BYTES 32768            // 16KB A + 16KB B
#define SMEM_BYTES (STAGES * STAGE_BYTES)

// ---- scratch (alloc-free rule: __device__ globals) ----
// transposed+rounded inputs [B][N][C]
__device__ float g_inA_t[(size_t)BATCH * NDIM * CDIM];
__device__ float g_inB_t[(size_t)BATCH * NDIM * CDIM];
// rounded weights
__device__ float g_WA_r [(size_t)EDIM * CDIM];
__device__ float g_WB_r [(size_t)EDIM * CDIM];
__device__ float g_WBh_r[(size_t)EDIM * CDIM];
__device__ float g_Wout_r[(size_t)CDIM * EDIM];
// intermediates (all tf32-rounded by producer)
__device__ float g_aproj_t[(size_t)BATCH * NDIM * EDIM];   // [pos][e]
__device__ float g_bp_t   [(size_t)BATCH * NDIM * EDIM];   // [pos][e]
__device__ float g_bh     [(size_t)BATCH * EDIM * NDIM];   // [e][pos]
__device__ float g_out1_t [(size_t)BATCH * NDIM * EDIM];   // [a][e]
__device__ float g_att_t  [(size_t)BATCH * NDIM * NDIM];   // rounded copy of att
__device__ float g_mean [CDIM];
__device__ float g_rstd [CDIM];

// ---- tf32 / mma helpers ----
__device__ __forceinline__ uint32_t f2tf32(float x) {
    uint32_t r; asm("cvt.rna.tf32.f32 %0, %1;" : "=r"(r) : "f"(x)); return r;
}
__device__ __forceinline__ float rndf(float x) { return __uint_as_float(f2tf32(x)); }

__device__ __forceinline__ void mma_tf32(float4& d,
                                         uint32_t a0, uint32_t a1, uint32_t a2, uint32_t a3,
                                         uint32_t b0, uint32_t b1) {
    asm volatile("mma.sync.aligned.m16n8k8.row.col.f32.tf32.tf32.f32 "
                 "{%0,%1,%2,%3}, {%4,%5,%6,%7}, {%8,%9}, {%0,%1,%2,%3};"
                 : "+f"(d.x), "+f"(d.y), "+f"(d.z), "+f"(d.w)
                 : "r"(a0), "r"(a1), "r"(a2), "r"(a3), "r"(b0), "r"(b1));
}
__device__ __forceinline__ void ldsm_x4(uint32_t& r0, uint32_t& r1,
                                        uint32_t& r2, uint32_t& r3, uint32_t addr) {
    asm volatile("ldmatrix.sync.aligned.m8n8.x4.shared.b16 {%0,%1,%2,%3}, [%4];"
                 : "=r"(r0), "=r"(r1), "=r"(r2), "=r"(r3) : "r"(addr));
}
__device__ __forceinline__ void cp16(uint32_t dst, const void* src) {
    asm volatile("cp.async.cg.shared.global [%0], [%1], 16;" :: "r"(dst), "l"(src));
}
#define CP_COMMIT() asm volatile("cp.async.commit_group;")
#define CP_WAIT1()  asm volatile("cp.async.wait_group 1;")

// swizzle for 128B rows: XOR byte-col bits[4:6] with row bits[0:2]
__device__ __forceinline__ uint32_t swz(uint32_t row, uint32_t colbyte) {
    return (row << 7) | (colbyte ^ ((row & 7) << 4));
}

// ============================================================================
// Pipelined TF32 GEMM. Both operands contraction-contiguous and pre-rounded:
//   A[m][k] (lda), B[n][k] (ldb)  ->  C[m][n] = alpha * sum_k A*B
// 128x128 block tile, BK=32, 3-stage cp.async pipeline, 256 threads,
// 8 warps (2x4), warp tile 64x32, m16n8k8, ldmatrix-fed fragments.
// ============================================================================
template<bool ROUND>
__global__ __launch_bounds__(256, 2)
void gemm_pipe(const float* __restrict__ Ag, const float* __restrict__ Bg,
               float* __restrict__ Cg, int K, int lda, int ldb, int ldc,
               size_t sA, size_t sB, size_t sC, float alpha)
{
    extern __shared__ __align__(16) char dynsmem[];
    const uint32_t smBase = (uint32_t)__cvta_generic_to_shared(dynsmem);

    const float* A = Ag + (size_t)blockIdx.z * sA;
    const float* B = Bg + (size_t)blockIdx.z * sB;
    float*       C = Cg + (size_t)blockIdx.z * sC;

    const int m0 = blockIdx.y * 128;
    const int n0 = blockIdx.x * 128;
    const int tid  = threadIdx.x;
    const int lane = tid & 31;
    const int wid  = tid >> 5;
    const int warp_m = wid >> 2;   // 0..1  -> 64 m-rows
    const int warp_n = wid & 3;    // 0..3  -> 32 n-cols

    // per-lane ldmatrix row/half selectors (same mapping as validated R3)
    const int a_row = (lane & 7) + ((lane >> 3) & 1) * 8;
    const int a_ts  = ((lane >> 4) & 1) << 4;
    const int b_row = (lane & 7) + ((lane >> 4) & 1) * 8;
    const int b_ts  = ((lane >> 3) & 1) << 4;

    uint32_t aRow[4], bRow[2];
    #pragma unroll
    for (int i = 0; i < 4; i++) aRow[i] = (uint32_t)((warp_m * 64 + i * 16 + a_row) << 7);
    #pragma unroll
    for (int j = 0; j < 2; j++) bRow[j] = (uint32_t)((warp_n * 32 + j * 16 + b_row) << 7) + 16384u;
    const uint32_t aSwz = (uint32_t)((a_row & 7) << 4);
    const uint32_t bSwz = (uint32_t)((b_row & 7) << 4);

    // cp.async staging coords (4 chunks per operand per thread)
    const int ld_row = tid >> 3;                 // 0..31 (+32 per r)
    const int ld_kq  = (tid & 7) << 2;           // k offset 0,4,..,28
    const uint32_t ld_dst = swz((uint32_t)ld_row, (uint32_t)(ld_kq << 2));

    const int T = K >> 5;

    float4 acc[4][4];
    #pragma unroll
    for (int i = 0; i < 4; i++)
        #pragma unroll
        for (int j = 0; j < 4; j++)
            acc[i][j] = make_float4(0.f, 0.f, 0.f, 0.f);

    // ---- prologue: fill stages 0,1 ----
    #pragma unroll
    for (int s = 0; s < 2; s++) {
        const uint32_t sa = smBase + s * STAGE_BYTES;
        const int k0 = s * 32;
        #pragma unroll
        for (int r = 0; r < 4; r++) {
            int row = ld_row + r * 32;
            cp16(sa + ld_dst + (uint32_t)(r * 32 * 128),
                 A + (size_t)(m0 + row) * lda + (k0 + ld_kq));
            cp16(sa + 16384u + ld_dst + (uint32_t)(r * 32 * 128),
                 B + (size_t)(n0 + row) * ldb + (k0 + ld_kq));
        }
        CP_COMMIT();
    }

    int stage = 0;
    for (int t = 0; t < T; t++) {
        CP_WAIT1();
        __syncthreads();

        // issue t+2
        if (t + 2 < T) {
            int s2 = stage + 2; if (s2 >= STAGES) s2 -= STAGES;
            const uint32_t sa = smBase + s2 * STAGE_BYTES;
            const int k0 = (t + 2) * 32;
            #pragma unroll
            for (int r = 0; r < 4; r++) {
                int row = ld_row + r * 32;
                cp16(sa + ld_dst + (uint32_t)(r * 32 * 128),
                     A + (size_t)(m0 + row) * lda + (k0 + ld_kq));
                cp16(sa + 16384u + ld_dst + (uint32_t)(r * 32 * 128),
                     B + (size_t)(n0 + row) * ldb + (k0 + ld_kq));
            }
        }
        CP_COMMIT();

        // ---- compute current stage ----
        const uint32_t sb = smBase + stage * STAGE_BYTES;
        #pragma unroll
        for (int ks = 0; ks < 4; ks++) {
            const uint32_t aCol = ((uint32_t)(ks * 32) + a_ts) ^ aSwz;
            const uint32_t bCol = ((uint32_t)(ks * 32) + b_ts) ^ bSwz;
            uint32_t af[4][4], bf[2][4];
            #pragma unroll
            for (int i = 0; i < 4; i++)
                ldsm_x4(af[i][0], af[i][1], af[i][2], af[i][3], sb + aRow[i] + aCol);
            #pragma unroll
            for (int j = 0; j < 2; j++)
                ldsm_x4(bf[j][0], bf[j][1], bf[j][2], bf[j][3], sb + bRow[j] + bCol);
            #pragma unroll
            for (int i = 0; i < 4; i++) {
                #pragma unroll
                for (int jn = 0; jn < 4; jn++) {
                    int jx = jn >> 1, h = (jn & 1) << 1;
                    mma_tf32(acc[i][jn], af[i][0], af[i][1], af[i][2], af[i][3],
                             bf[jx][h], bf[jx][h + 1]);
                }
            }
        }
        stage++; if (stage >= STAGES) stage -= STAGES;
    }

    // ---- epilogue ----
    const int g = lane >> 2, tq = lane & 3;
    const int mw = m0 + warp_m * 64;
    const int nw = n0 + warp_n * 32;
    #pragma unroll
    for (int i = 0; i < 4; i++) {
        #pragma unroll
        for (int jn = 0; jn < 4; jn++) {
            int row = mw + i * 16 + g;
            int col = nw + jn * 8 + 2 * tq;
            float2 v0 = make_float2(acc[i][jn].x * alpha, acc[i][jn].y * alpha);
            float2 v1 = make_float2(acc[i][jn].z * alpha, acc[i][jn].w * alpha);
            if (ROUND) {
                v0.x = rndf(v0.x); v0.y = rndf(v0.y);
                v1.x = rndf(v1.x); v1.y = rndf(v1.y);
            }
            *(float2*)(C + (size_t)row * ldc + col)       = v0;
            *(float2*)(C + (size_t)(row + 8) * ldc + col) = v1;
        }
    }
}

// ============================================================================
// transpose + tf32-round: [C][N] -> [N][C] per batch. grid (N/32, C/32, B),
// block (32, 8).
// ============================================================================
__global__ __launch_bounds__(256)
void transpose_round(const float* __restrict__ in, float* __restrict__ outp)
{
    __shared__ float tile[32][33];
    const float* src = in  + (size_t)blockIdx.z * CDIM * NDIM;
    float*       dst = outp + (size_t)blockIdx.z * NDIM * CDIM;

    int x = blockIdx.x * 32 + threadIdx.x;           // n
    #pragma unroll
    for (int i = 0; i < 4; i++) {
        int c = blockIdx.y * 32 + threadIdx.y + i * 8;
        tile[threadIdx.y + i * 8][threadIdx.x] = src[(size_t)c * NDIM + x];
    }
    __syncthreads();
    int xo = blockIdx.y * 32 + threadIdx.x;          // c
    #pragma unroll
    for (int i = 0; i < 4; i++) {
        int n = blockIdx.x * 32 + threadIdx.y + i * 8;
        dst[(size_t)n * CDIM + xo] = rndf(tile[threadIdx.x][threadIdx.y + i * 8]);
    }
}

// elementwise tf32 round copy (n multiple of 1024)
__global__ __launch_bounds__(256)
void round_copy(const float* __restrict__ in, float* __restrict__ outp)
{
    size_t i = ((size_t)blockIdx.x * 256 + threadIdx.x) * 4;
    float4 v = *(const float4*)(in + i);
    v.x = rndf(v.x); v.y = rndf(v.y); v.z = rndf(v.z); v.w = rndf(v.w);
    *(float4*)(outp + i) = v;
}

// ============================================================================
// In-place row softmax over rows of length 2048 + rounded copy to att_t.
// ============================================================================
__global__ __launch_bounds__(256)
void softmax2048(float* __restrict__ att, float* __restrict__ att_t)
{
    float* p  = att   + (size_t)blockIdx.x * NDIM;
    float* pt = att_t + (size_t)blockIdx.x * NDIM;
    const int t = threadIdx.x;

    float x[8];
    *(float4*)&x[0] = *(const float4*)(p + t * 4);
    *(float4*)&x[4] = *(const float4*)(p + 1024 + t * 4);

    float mx = x[0];
    #pragma unroll
    for (int i = 1; i < 8; i++) mx = fmaxf(mx, x[i]);
    #pragma unroll
    for (int o = 16; o > 0; o >>= 1) mx = fmaxf(mx, __shfl_xor_sync(0xffffffffu, mx, o));

    __shared__ float rmax[8], rsum[8];
    if ((t & 31) == 0) rmax[t >> 5] = mx;
    __syncthreads();
    mx = rmax[0];
    #pragma unroll
    for (int w = 1; w < 8; w++) mx = fmaxf(mx, rmax[w]);

    float s = 0.f;
    #pragma unroll
    for (int i = 0; i < 8; i++) { x[i] = __expf(x[i] - mx); s += x[i]; }
    #pragma unroll
    for (int o = 16; o > 0; o >>= 1) s += __shfl_xor_sync(0xffffffffu, s, o);
    if ((t & 31) == 0) rsum[t >> 5] = s;
    __syncthreads();
    s = 0.f;
    #pragma unroll
    for (int w = 0; w < 8; w++) s += rsum[w];

    float inv = 1.0f / s;
    float r[8];
    #pragma unroll
    for (int i = 0; i < 8; i++) { x[i] *= inv; r[i] = rndf(x[i]); }
    *(float4*)(p + t * 4)         = *(float4*)&x[0];
    *(float4*)(p + 1024 + t * 4)  = *(float4*)&x[4];
    *(float4*)(pt + t * 4)        = *(float4*)&r[0];
    *(float4*)(pt + 1024 + t * 4) = *(float4*)&r[4];
}

// ============================================================================
// BatchNorm: per-channel stats over (batch, positions).
// ============================================================================
__global__ __launch_bounds__(256)
void bn_stats(const float* __restrict__ outp,
              float* __restrict__ mean, float* __restrict__ rstd)
{
    const int c = blockIdx.x;
    const int t = threadIdx.x;
    float s = 0.f, ss = 0.f;
    for (int b = 0; b < BATCH; b++) {
        const float* p = outp + (size_t)b * CDIM * NDIM + (size_t)c * NDIM;
        for (int a = t; a < NDIM; a += 256) {
            float x = p[a];
            s += x;
            ss = fmaf(x, x, ss);
        }
    }
    #pragma unroll
    for (int o = 16; o > 0; o >>= 1) {
        s  += __shfl_xor_sync(0xffffffffu, s,  o);
        ss += __shfl_xor_sync(0xffffffffu, ss, o);
    }
    __shared__ float rs[8], rss[8];
    if ((t & 31) == 0) { rs[t >> 5] = s; rss[t >> 5] = ss; }
    __syncthreads();
    if (t == 0) {
        float S = 0.f, SS = 0.f;
        #pragma unroll
        for (int w = 0; w < 8; w++) { S += rs[w]; SS += rss[w]; }
        const float invN = 1.0f / (float)(BATCH * NDIM);
        float m = S * invN;
        float var = SS * invN - m * m;
        mean[c] = m;
        rstd[c] = rsqrtf(var + 1e-5f);
    }
}

__global__ __launch_bounds__(256)
void bn_norm(float* __restrict__ outp,
             const float* __restrict__ mean, const float* __restrict__ rstd,
             const float* __restrict__ gamma, const float* __restrict__ beta)
{
    size_t i = ((size_t)blockIdx.x * 256 + threadIdx.x) * 4;
    int c = (int)((i / NDIM) % CDIM);
    float m = mean[c], r = rstd[c];
    float sc = r * gamma[c];
    float sh = beta[c] - m * sc;
    float4 v = *(float4*)(outp + i);
    v.x = fmaf(v.x, sc, sh);
    v.y = fmaf(v.y, sc, sh);
    v.z = fmaf(v.z, sc, sh);
    v.w = fmaf(v.w, sc, sh);
    *(float4*)(outp + i) = v;
}

// ============================================================================
extern "C" void kernel_launch(void* const* d_in, const int* in_sizes, int n_in,
                              void* d_out, int out_size)
{
    (void)in_sizes; (void)n_in; (void)out_size;
    const float* input_A = (const float*)d_in[0];
    const float* input_B = (const float*)d_in[1];
    const float* W_A     = (const float*)d_in[2];
    const float* W_B     = (const float*)d_in[3];
    const float* W_Bh    = (const float*)d_in[4];
    const float* W_out   = (const float*)d_in[5];
    const float* gamma   = (const float*)d_in[6];
    const float* beta    = (const float*)d_in[7];

    float* out = (float*)d_out;
    float* att = out + (size_t)BATCH * CDIM * NDIM;

    float *inA_t, *inB_t, *WA_r, *WB_r, *WBh_r, *Wout_r;
    float *aproj_t, *bp_t, *bh, *out1_t, *att_t, *mean, *rstd;
    cudaGetSymbolAddress((void**)&inA_t,   g_inA_t);
    cudaGetSymbolAddress((void**)&inB_t,   g_inB_t);
    cudaGetSymbolAddress((void**)&WA_r,    g_WA_r);
    cudaGetSymbolAddress((void**)&WB_r,    g_WB_r);
    cudaGetSymbolAddress((void**)&WBh_r,   g_WBh_r);
    cudaGetSymbolAddress((void**)&Wout_r,  g_Wout_r);
    cudaGetSymbolAddress((void**)&aproj_t, g_aproj_t);
    cudaGetSymbolAddress((void**)&bp_t,    g_bp_t);
    cudaGetSymbolAddress((void**)&bh,      g_bh);
    cudaGetSymbolAddress((void**)&out1_t,  g_out1_t);
    cudaGetSymbolAddress((void**)&att_t,   g_att_t);
    cudaGetSymbolAddress((void**)&mean,    g_mean);
    cudaGetSymbolAddress((void**)&rstd,    g_rstd);

    cudaFuncSetAttribute(gemm_pipe<true>,  cudaFuncAttributeMaxDynamicSharedMemorySize, SMEM_BYTES);
    cudaFuncSetAttribute(gemm_pipe<false>, cudaFuncAttributeMaxDynamicSharedMemorySize, SMEM_BYTES);

    const dim3 blk(256);
    const size_t sNC = (size_t)NDIM * CDIM;
    const size_t sNE = (size_t)NDIM * EDIM;
    const size_t sEN = (size_t)EDIM * NDIM;
    const size_t sCN = (size_t)CDIM * NDIM;
    const size_t sNN = (size_t)NDIM * NDIM;

    // 0) preprocess: transpose+round inputs, round weights
    dim3 gt(NDIM / 32, CDIM / 32, BATCH);
    transpose_round<<<gt, dim3(32, 8)>>>(input_A, inA_t);
    transpose_round<<<gt, dim3(32, 8)>>>(input_B, inB_t);
    round_copy<<<(EDIM * CDIM) / 1024, blk>>>(W_A,   WA_r);
    round_copy<<<(EDIM * CDIM) / 1024, blk>>>(W_B,   WB_r);
    round_copy<<<(EDIM * CDIM) / 1024, blk>>>(W_Bh,  WBh_r);
    round_copy<<<(CDIM * EDIM) / 1024, blk>>>(W_out, Wout_r);

    // 1) projections
    // aproj_t[pos][e] : m=pos(2048), n=e(256), k=c(512); A=inA_t, B=W_A
    dim3 gpa(EDIM / 128, NDIM / 128, BATCH);
    gemm_pipe<true><<<gpa, blk, SMEM_BYTES>>>(inA_t, WA_r, aproj_t, CDIM, CDIM, CDIM, EDIM, sNC, 0, sNE, 1.f);
    // bp_t[pos][e]
    gemm_pipe<true><<<gpa, blk, SMEM_BYTES>>>(inB_t, WB_r, bp_t,    CDIM, CDIM, CDIM, EDIM, sNC, 0, sNE, 1.f);
    // bh[e][pos] : m=e(256), n=pos(2048), k=c(512); A=W_Bh, B=inB_t
    dim3 gpb(NDIM / 128, EDIM / 128, BATCH);
    gemm_pipe<true><<<gpb, blk, SMEM_BYTES>>>(WBh_r, inB_t, bh,     CDIM, CDIM, CDIM, NDIM, 0, sNC, sEN, 1.f);

    // 2) h[a][b] = (aproj_t · bp_t^T)/16 : m=a, n=b, k=e(256)
    dim3 gh(NDIM / 128, NDIM / 128, BATCH);
    gemm_pipe<false><<<gh, blk, SMEM_BYTES>>>(aproj_t, bp_t, att, EDIM, EDIM, EDIM, NDIM, sNE, sNE, sNN, 0.0625f);

    // 3) softmax (+ rounded copy)
    softmax2048<<<BATCH * NDIM, blk>>>(att, att_t);

    // 4) out1_t[a][e] : m=a(2048), n=e(256), k=m-pos(2048); A=att_t, B=bh
    dim3 g4(EDIM / 128, NDIM / 128, BATCH);
    gemm_pipe<true><<<g4, blk, SMEM_BYTES>>>(att_t, bh, out1_t, NDIM, NDIM, NDIM, EDIM, sNN, sEN, sNE, 1.f);

    // 5) out[c][a] : m=c(512), n=a(2048), k=e(256); A=W_out, B=out1_t
    dim3 g5(NDIM / 128, CDIM / 128, BATCH);
    gemm_pipe<false><<<g5, blk, SMEM_BYTES>>>(Wout_r, out1_t, out, EDIM, EDIM, EDIM, NDIM, 0, sNE, sCN, 1.f);

    // 6) BatchNorm
    bn_stats<<<CDIM, blk>>>(out, mean, rstd);
    bn_norm<<<(BATCH * CDIM * NDIM) / 1024, blk>>>(out, mean, rstd, gamma, beta);
}